// round 16
// baseline (speedup 1.0000x reference)
#include <cuda_runtime.h>
#include <cuda_fp16.h>
#include <math.h>

// ---------------------------------------------------------------------------
// Problem constants
// ---------------------------------------------------------------------------
#define BATCH 16
#define NH    128
#define L0    16384
#define KS    4
#define DEPTHS 13
#define LMAX  8192
#define CIN   129

// ---- HMMA kernel config (depths 0..5) ----
#define NT      64          // t's per block (8 n-tiles of 8)
#define NK16    32          // k16 fragments (K = 512)
#define NMT     24          // m-tiles (384 rows / 16)
#define MMA_NTH 512         // 16 warps
#define BH_WORDS (NK16 * 8 * 32 * 2)     // 16384 u32 (single fp16 B)
#define RAWP    132                      // raw tile pitch (halves)

// ---- scalar tail config (depths 6..12) ----
#define TT_OUT 16
#define TTPT   8
#define TTIN   (2*TT_OUT + 2)

typedef unsigned long long ull;
typedef unsigned int u32;

// ---------------------------------------------------------------------------
// Device scratch
// ---------------------------------------------------------------------------
__device__ float  g_bufA[(size_t)BATCH * NH * LMAX];
__device__ float  g_bufB[(size_t)BATCH * NH * LMAX];
__device__ float4 g_W4[CIN * 3 * NH];               // tail weights (fp32)
__device__ u32    g_Wfrag[NK16 * NMT * 32 * 4];     // a-frag-ordered fp16 W
__device__ float  g_Wd[384 * 4];                    // depth-channel weights
__device__ float  g_capture[BATCH * NH];
__device__ int    g_Nseq[BATCH][DEPTHS + 1];
__device__ int    g_finish[BATCH];
__device__ int    g_rank[BATCH];

// ---------------------------------------------------------------------------
// helpers
// ---------------------------------------------------------------------------
__device__ __forceinline__ ull fma2(ull a, ull b, ull c)
{
    ull d;
    asm("fma.rn.f32x2 %0, %1, %2, %3;" : "=l"(d) : "l"(a), "l"(b), "l"(c));
    return d;
}
__device__ __forceinline__ void unpack2f(ull v, float& lo, float& hi)
{
    asm("mov.b64 {%0, %1}, %2;" : "=f"(lo), "=f"(hi) : "l"(v));
}
__device__ __forceinline__ void mma_f16(float* d, const u32* a, const u32* b)
{
    asm volatile(
        "mma.sync.aligned.m16n8k16.row.col.f32.f16.f16.f32 "
        "{%0,%1,%2,%3}, {%4,%5,%6,%7}, {%8,%9}, {%0,%1,%2,%3};"
        : "+f"(d[0]), "+f"(d[1]), "+f"(d[2]), "+f"(d[3])
        : "r"(a[0]), "r"(a[1]), "r"(a[2]), "r"(a[3]), "r"(b[0]), "r"(b[1]));
}

// ---------------------------------------------------------------------------
// Prep: N recurrence, finish depth, stable rank
// ---------------------------------------------------------------------------
__global__ void prep_meta_kernel(const int* __restrict__ N)
{
    __shared__ int fin[BATCH];
    int b = threadIdx.x;
    if (b < BATCH) {
        int n = N[b];
        g_Nseq[b][0] = n;
        int f = DEPTHS - 1;
        bool done = false;
        #pragma unroll
        for (int d = 0; d < DEPTHS; ++d) {
            int m = n - KS; if (m < 0) m = 0;
            n = (m + 1) / 2 + 1;
            g_Nseq[b][d + 1] = n;
            if (!done && n <= 1) { f = d; done = true; }
        }
        fin[b] = f;
        g_finish[b] = f;
    }
    __syncthreads();
    if (b < BATCH) {
        int f = fin[b];
        int r = 0;
        #pragma unroll
        for (int j = 0; j < BATCH; ++j)
            if (fin[j] < f || (fin[j] == f && j < b)) r++;
        g_rank[b] = r;
    }
}

// ---------------------------------------------------------------------------
// Prep: tail weights (g_W4)
// ---------------------------------------------------------------------------
__global__ void prep_wt_kernel(const float* __restrict__ W)
{
    int i = blockIdx.x * blockDim.x + threadIdx.x;
    if (i < CIN * 3 * NH) {
        int o    = i & 127;
        int gate = (i >> 7) % 3;
        int c    = i / (3 * NH);
        int j    = gate * NH + o;
        const float4* src = reinterpret_cast<const float4*>(W);
        g_W4[i] = src[j * CIN + c];
    }
}

// ---------------------------------------------------------------------------
// Prep: a-fragment-ordered fp16 weights + depth-channel weights.
// ---------------------------------------------------------------------------
__global__ void prep_wfrag_kernel(const float* __restrict__ W)
{
    int idx = blockIdx.x * blockDim.x + threadIdx.x;
    const int TOT = NK16 * NMT * 32 * 4;
    if (idx < TOT) {
        int r     = idx & 3;
        int lane  = (idx >> 2) & 31;
        int mtile = (idx >> 7) % NMT;
        int k16   = (idx >> 7) / NMT;
        u32 out = 0;
        #pragma unroll
        for (int i = 0; i < 2; ++i) {
            int m = mtile * 16 + (lane >> 2) + 8 * (r & 1);
            int k = k16 * 16 + (lane & 3) * 2 + 8 * (r >> 1) + i;
            int c = k >> 2, kap = k & 3;
            float w = W[m * (CIN * KS) + c * KS + kap];
            __half wh = __float2half_rn(w);
            out |= ((u32)*reinterpret_cast<unsigned short*>(&wh)) << (16 * i);
        }
        g_Wfrag[idx] = out;
    }
    if (idx < 384 * 4) {
        int m = idx >> 2, k = idx & 3;
        g_Wd[idx] = W[m * (CIN * KS) + 128 * KS + k];
    }
}

// ---------------------------------------------------------------------------
// HMMA depth step (d = 0..5): one block = 64 t's of one batch, full M=384.
// B built in two stages: coalesced fp16 raw tile -> frag words via LDS.32.
// ---------------------------------------------------------------------------
__global__ __launch_bounds__(MMA_NTH, 1)
void conv_mma_kernel(const float* __restrict__ hin,
                     int insel, int outsel, int in_stride,
                     int Lc, int Lout, int depth, float logd,
                     const float* __restrict__ bias)
{
    const int b  = blockIdx.y;
    const int t0 = blockIdx.x * NT;
    if (t0 >= g_Nseq[b][depth + 1]) return;

    const float* in = (insel == 0) ? hin : (insel == 1 ? g_bufA : g_bufB);
    float* out = (outsel == 1) ? g_bufA : g_bufB;

    extern __shared__ __align__(16) char smem[];
    u32*    Bh   = reinterpret_cast<u32*>(smem);
    __half* rawh = reinterpret_cast<__half*>(Bh + BH_WORDS);  // [128][RAWP]

    const int tid = threadIdx.x;
    const int V = min(Lc, g_Nseq[b][depth]);
    const float* xb = in + (size_t)b * NH * in_stride;

    // ---- stage 1: coalesced raw x tile -> fp16 smem ----
    for (int i = tid; i < 128 * 33; i += MMA_NTH) {
        int c = i / 33, q = i - c * 33;
        int pos0 = 2 * t0 + 4 * q;
        const float* row = xb + (size_t)c * in_stride;
        float4 v;
        if (pos0 + 3 < V) {
            v = *reinterpret_cast<const float4*>(row + pos0);
        } else {
            v.x = (pos0     < V) ? row[pos0]     : 0.f;
            v.y = (pos0 + 1 < V) ? row[pos0 + 1] : 0.f;
            v.z = (pos0 + 2 < V) ? row[pos0 + 2] : 0.f;
            v.w = (pos0 + 3 < V) ? row[pos0 + 3] : 0.f;
        }
        __half2 p0 = __floats2half2_rn(v.x, v.y);
        __half2 p1 = __floats2half2_rn(v.z, v.w);
        ull w = (ull)(*reinterpret_cast<u32*>(&p0))
              | ((ull)(*reinterpret_cast<u32*>(&p1)) << 32);
        *reinterpret_cast<ull*>(rawh + c * RAWP + 4 * q) = w;
    }
    __syncthreads();

    // ---- stage 2: build B frag words (1 LDS.32 each) ----
    for (int s = tid; s < BH_WORDS; s += MMA_NTH) {
        int lane2 = (s >> 1) & 31;
        int c  = ((s >> 9) << 2) + ((s & 1) << 1) + ((lane2 & 2) >> 1);
        int px = ((((s >> 6) & 7) << 3) + (lane2 >> 2)) * 2 + ((lane2 & 1) << 1);
        Bh[s] = *reinterpret_cast<const u32*>(rawh + c * RAWP + px);
    }
    __syncthreads();

    const int wid  = tid >> 5;
    const int lane = tid & 31;
    const int mw   = wid >> 1;     // 0..7
    const int nw   = wid & 1;      // 0..1

    float acc[3][4][4];
    #pragma unroll
    for (int g = 0; g < 3; ++g)
        #pragma unroll
        for (int ni = 0; ni < 4; ++ni)
            #pragma unroll
            for (int r = 0; r < 4; ++r) acc[g][ni][r] = 0.f;

    // ---- mainloop over 32 k16 fragments ----
    #pragma unroll 2
    for (int k16 = 0; k16 < NK16; ++k16) {
        u32 ah[3][4];
        #pragma unroll
        for (int g = 0; g < 3; ++g) {
            int mtile = g * 8 + mw;
            uint4 vh = *reinterpret_cast<const uint4*>(
                g_Wfrag + ((k16 * NMT + mtile) * 32 + lane) * 4);
            ah[g][0] = vh.x; ah[g][1] = vh.y; ah[g][2] = vh.z; ah[g][3] = vh.w;
        }
        u32 bh[4][2];
        #pragma unroll
        for (int ni = 0; ni < 4; ++ni) {
            int ntile = nw * 4 + ni;
            uint2 vb = *reinterpret_cast<const uint2*>(
                Bh + ((k16 * 8 + ntile) * 32 + lane) * 2);
            bh[ni][0] = vb.x; bh[ni][1] = vb.y;
        }
        #pragma unroll
        for (int g = 0; g < 3; ++g)
            #pragma unroll
            for (int ni = 0; ni < 4; ++ni)
                mma_f16(acc[g][ni], ah[g], bh[ni]);
    }

    // ---- epilogue: bias + depth channel + gating ----
    const int rowa = 16 * mw + (lane >> 2);
    const int rowb = rowa + 8;
    const float biasv[2][3] = {
        { bias[rowa], bias[NH + rowa], bias[2 * NH + rowa] },
        { bias[rowb], bias[NH + rowb], bias[2 * NH + rowb] } };
    float4 wd[2][3];
    float fsum[2][3];
    #pragma unroll
    for (int rs = 0; rs < 2; ++rs)
        #pragma unroll
        for (int g = 0; g < 3; ++g) {
            int row = rs ? rowb : rowa;
            wd[rs][g] = *reinterpret_cast<const float4*>(g_Wd + (g * 128 + row) * 4);
            fsum[rs][g] = logd * (wd[rs][g].x + wd[rs][g].y + wd[rs][g].z + wd[rs][g].w);
        }

    const int fin_here = (g_finish[b] == depth);
    #pragma unroll
    for (int ni = 0; ni < 4; ++ni) {
        int col0 = t0 + 32 * nw + ni * 8 + (lane & 3) * 2;
        #pragma unroll
        for (int rs = 0; rs < 2; ++rs) {
            int row = rs ? rowb : rowa;
            float* orow = out + ((size_t)b * NH + row) * LMAX;
            #pragma unroll
            for (int cc = 0; cc < 2; ++cc) {
                int col = col0 + cc;
                if (col < Lout) {
                    int ci = rs * 2 + cc;
                    float dt[3];
                    int p2 = 2 * col;
                    if (p2 + 3 < V) {
                        dt[0] = fsum[rs][0]; dt[1] = fsum[rs][1]; dt[2] = fsum[rs][2];
                    } else {
                        float m0 = (p2 < V) ? logd : 0.f, m1 = (p2+1 < V) ? logd : 0.f;
                        float m2 = (p2+2 < V) ? logd : 0.f, m3 = (p2+3 < V) ? logd : 0.f;
                        #pragma unroll
                        for (int g = 0; g < 3; ++g)
                            dt[g] = wd[rs][g].x*m0 + wd[rs][g].y*m1
                                  + wd[rs][g].z*m2 + wd[rs][g].w*m3;
                    }
                    float l  = acc[0][ni][ci] + biasv[rs][0] + dt[0];
                    float rr = acc[1][ni][ci] + biasv[rs][1] + dt[1];
                    float ga = acc[2][ni][ci] + biasv[rs][2] + dt[2];
                    float gv = 1.0f / (1.0f + __expf(-ga));
                    float rv = tanhf(rr);
                    float hn = l * gv + rv * (1.0f - gv);
                    orow[col] = hn;
                    if (col == 0 && fin_here) g_capture[b * NH + row] = hn;
                }
            }
        }
    }
}

// ---------------------------------------------------------------------------
// Scalar tail step (d = 6..12): R2-proven kernel (fp32 exact)
// ---------------------------------------------------------------------------
__global__ __launch_bounds__(256)
void conv_tail_kernel(int insel, int outsel,
                      int Lc, int Lout, int depth, float logd,
                      const float* __restrict__ bias)
{
    const int b  = blockIdx.y;
    const int t0 = blockIdx.x * TT_OUT;

    const int Nn = g_Nseq[b][depth + 1];
    if (t0 >= Nn) return;

    const float* in = (insel == 1) ? g_bufA : g_bufB;
    float* out = (outsel == 1) ? g_bufA : g_bufB;

    __shared__ float tile[CIN][TTIN];

    const int V = min(Lc, g_Nseq[b][depth]);
    const float* inb = in + (size_t)b * NH * LMAX;

    for (int i = threadIdx.x; i < CIN * TTIN; i += 256) {
        int c = i / TTIN;
        int x = i - c * TTIN;
        int pos = 2 * t0 + x;
        float v = 0.0f;
        if (pos < V) v = (c < NH) ? inb[(size_t)c * LMAX + pos] : logd;
        tile[c][x] = v;
    }
    __syncthreads();

    const int o    = threadIdx.x & 127;
    const int half = threadIdx.x >> 7;
    const int tl0  = half * TTPT;

    ull accl[TTPT], accr[TTPT], accg[TTPT];
    #pragma unroll
    for (int tt = 0; tt < TTPT; ++tt) { accl[tt] = 0ull; accr[tt] = 0ull; accg[tt] = 0ull; }

    const ulonglong2* wbase = reinterpret_cast<const ulonglong2*>(g_W4);

    #pragma unroll 1
    for (int c = 0; c < CIN; ++c) {
        const ulonglong2 wl = wbase[(c * 3 + 0) * NH + o];
        const ulonglong2 wr = wbase[(c * 3 + 1) * NH + o];
        const ulonglong2 wg = wbase[(c * 3 + 2) * NH + o];
        const ull* xr = reinterpret_cast<const ull*>(&tile[c][2 * tl0]);
        ull x0 = xr[0];
        #pragma unroll
        for (int tt = 0; tt < TTPT; ++tt) {
            ull x1 = xr[tt + 1];
            accl[tt] = fma2(wl.x, x0, accl[tt]);
            accl[tt] = fma2(wl.y, x1, accl[tt]);
            accr[tt] = fma2(wr.x, x0, accr[tt]);
            accr[tt] = fma2(wr.y, x1, accr[tt]);
            accg[tt] = fma2(wg.x, x0, accg[tt]);
            accg[tt] = fma2(wg.y, x1, accg[tt]);
            x0 = x1;
        }
    }

    const float bl = bias[o], br = bias[NH + o], bg = bias[2 * NH + o];
    const int fin_here = (g_finish[b] == depth);
    float* outb = out + ((size_t)b * NH + o) * LMAX;

    #pragma unroll
    for (int tt = 0; tt < TTPT; ++tt) {
        int t = t0 + tl0 + tt;
        if (t < Lout) {
            float lo, hi;
            unpack2f(accl[tt], lo, hi); float l  = lo + hi + bl;
            unpack2f(accr[tt], lo, hi); float rr = lo + hi + br;
            unpack2f(accg[tt], lo, hi); float ga = lo + hi + bg;
            float gv = 1.0f / (1.0f + __expf(-ga));
            float rv = tanhf(rr);
            float hn = l * gv + rv * (1.0f - gv);
            outb[t] = hn;
            if (t == 0 && fin_here) g_capture[b * NH + o] = hn;
        }
    }
}

// ---------------------------------------------------------------------------
// Final: out[rank[b]] = capture[b]
// ---------------------------------------------------------------------------
__global__ void finalize_kernel(float* __restrict__ out)
{
    int b = blockIdx.x;
    int o = threadIdx.x;
    out[g_rank[b] * NH + o] = g_capture[b * NH + o];
}

// ---------------------------------------------------------------------------
// Launch
// ---------------------------------------------------------------------------
extern "C" void kernel_launch(void* const* d_in, const int* in_sizes, int n_in,
                              void* d_out, int out_size)
{
    const float* h    = (const float*)d_in[0];
    const int*   N    = (const int*)  d_in[1];
    const float* W    = (const float*)d_in[2];
    const float* bias = (const float*)d_in[3];
    float* out = (float*)d_out;

    // Bh (65536) + raw fp16 tile (128*132*2 = 33792) = 99328 B
    const int SMEM_DYN = BH_WORDS * (int)sizeof(u32) + 128 * RAWP * 2;
    cudaFuncSetAttribute(conv_mma_kernel,
                         cudaFuncAttributeMaxDynamicSharedMemorySize, SMEM_DYN);

    prep_meta_kernel<<<1, 32>>>(N);
    prep_wt_kernel<<<(CIN * 3 * NH + 255) / 256, 256>>>(W);
    prep_wfrag_kernel<<<(NK16 * NMT * 32 * 4 + 255) / 256, 256>>>(W);

    static const int Lin[DEPTHS]   = {16384, 8191, 4095, 2047, 1023, 511, 255,
                                      127, 63, 31, 15, 7, 3};
    static const int LoutA[DEPTHS] = {8191, 4095, 2047, 1023, 511, 255, 127,
                                      63, 31, 15, 7, 3, 1};

    for (int d = 0; d < DEPTHS; ++d) {
        int insel  = (d == 0) ? 0 : ((d & 1) ? 1 : 2);
        int outsel = (d & 1) ? 2 : 1;
        int in_stride = (d == 0) ? L0 : LMAX;
        float logd = log1pf((float)d);
        if (d <= 5) {
            dim3 grid((LoutA[d] + NT - 1) / NT, BATCH);
            conv_mma_kernel<<<grid, MMA_NTH, SMEM_DYN>>>(
                h, insel, outsel, in_stride, Lin[d], LoutA[d], d, logd, bias);
        } else {
            dim3 grid((LoutA[d] + TT_OUT - 1) / TT_OUT, BATCH);
            conv_tail_kernel<<<grid, 256>>>(insel, outsel,
                                            Lin[d], LoutA[d], d, logd, bias);
        }
    }

    finalize_kernel<<<BATCH, NH>>>(out);
}